// round 9
// baseline (speedup 1.0000x reference)
#include <cuda_runtime.h>
#include <cstdint>

#define BB 4
#define SS 2048
#define NH 16
#define HD 64
#define DM 1024

// Scratch for Q/K/V in [B, H, S, hd] layout (device globals: allocation-free).
__device__ __align__(16) float g_q[BB * NH * SS * HD];
__device__ __align__(16) float g_k[BB * NH * SS * HD];
__device__ __align__(16) float g_v[BB * NH * SS * HD];

__device__ __forceinline__ unsigned f2tf(float x) {
    unsigned u;
    asm("cvt.rna.tf32.f32 %0, %1;" : "=r"(u) : "f"(x));
    return u;
}

__device__ __forceinline__ void mma_tf32(float* c, const unsigned* a, const unsigned* b) {
    asm volatile(
        "mma.sync.aligned.m16n8k8.row.col.f32.tf32.tf32.f32 "
        "{%0,%1,%2,%3}, {%4,%5,%6,%7}, {%8,%9}, {%0,%1,%2,%3};"
        : "+f"(c[0]), "+f"(c[1]), "+f"(c[2]), "+f"(c[3])
        : "r"(a[0]), "r"(a[1]), "r"(a[2]), "r"(a[3]), "r"(b[0]), "r"(b[1]));
}

// ---------------------------------------------------------------------------
// Kernel 1: fused QKV projection, tf32 MMA, 128x128 block tile, 8 warps
// (warp = 32m x 64n), double-buffered smem + register staging, 1 sync/chunk.
// ---------------------------------------------------------------------------
#define QSTR 36
#define QTILEW (128 * QSTR)           // words per tile buffer
#define QKV_SMEM_BYTES (4 * QTILEW * 4)   // 2 X bufs + 2 W bufs = 73728

__global__ __launch_bounds__(256) void qkv_kernel(
    const float* __restrict__ x,
    const float* __restrict__ Wq, const float* __restrict__ bq,
    const float* __restrict__ Wk, const float* __restrict__ bk,
    const float* __restrict__ Wv, const float* __restrict__ bv)
{
    extern __shared__ unsigned qsm[];
    unsigned* As[2] = { qsm, qsm + QTILEW };
    unsigned* Bs[2] = { qsm + 2 * QTILEW, qsm + 3 * QTILEW };

    const int tid = threadIdx.x;
    const int lane = tid & 31;
    const int w = tid >> 5;
    const int wm = w & 3;
    const int wn = w >> 2;
    const int mRow0 = wm * 32;
    const int nCol0 = wn * 64;
    const int t = lane & 3;
    const int g = lane >> 2;

    const int rowBase = blockIdx.y * 128;
    const int colBase = blockIdx.x * 128;      // combined cols [0,3072)
    const int mat = colBase >> 10;             // 0=Q 1=K 2=V (no straddle)
    const int colInMat = colBase & 1023;

    const float* W    = (mat == 0) ? Wq : (mat == 1) ? Wk : Wv;
    const float* bias = (mat == 0) ? bq : (mat == 1) ? bk : bv;
    float*       dst  = (mat == 0) ? g_q : (mat == 1) ? g_k : g_v;

    // Loader mapping: 128 rows x 32 k per tile; 4 float4 per thread.
    const int lrow = tid >> 3;          // wait: 256 threads, idx>>3 up to...
    // idx = tid + j*256, row = idx>>3 (0..127), c4 = (idx&7)*4
    float acc[2][8][4] = {};

    // Preload chunk 0.
    #pragma unroll
    for (int j = 0; j < 4; j++) {
        int idx = tid + j * 256;
        int row = idx >> 3;
        int c4 = (idx & 7) * 4;
        float4 a = *(const float4*)&x[(size_t)(rowBase + row) * DM + c4];
        unsigned* p = &As[0][row * QSTR + c4];
        p[0] = f2tf(a.x); p[1] = f2tf(a.y); p[2] = f2tf(a.z); p[3] = f2tf(a.w);
        float4 bw = *(const float4*)&W[(size_t)(colInMat + row) * DM + c4];
        unsigned* q = &Bs[0][row * QSTR + c4];
        q[0] = f2tf(bw.x); q[1] = f2tf(bw.y); q[2] = f2tf(bw.z); q[3] = f2tf(bw.w);
    }
    __syncthreads();
    (void)lrow;

    for (int c = 0; c < 32; c++) {
        const unsigned* Ac = As[c & 1];
        const unsigned* Bc = Bs[c & 1];
        unsigned* An = As[(c + 1) & 1];
        unsigned* Bn = Bs[(c + 1) & 1];
        const bool pf = (c < 31);

        // Prefetch next chunk into registers (LDGs issue before MMAs).
        float4 xa[4], wb[4];
        if (pf) {
            int kt = (c + 1) * 32;
            #pragma unroll
            for (int j = 0; j < 4; j++) {
                int idx = tid + j * 256;
                int row = idx >> 3;
                int c4 = (idx & 7) * 4;
                xa[j] = *(const float4*)&x[(size_t)(rowBase + row) * DM + kt + c4];
                wb[j] = *(const float4*)&W[(size_t)(colInMat + row) * DM + kt + c4];
            }
        }

        // 64 MMAs over 4 k-steps.
        #pragma unroll
        for (int kk = 0; kk < 4; kk++) {
            const int col = kk * 8 + t;
            unsigned a[2][4];
            #pragma unroll
            for (int mi = 0; mi < 2; mi++) {
                int r = mRow0 + mi * 16 + g;
                a[mi][0] = Ac[r * QSTR + col];
                a[mi][1] = Ac[(r + 8) * QSTR + col];
                a[mi][2] = Ac[r * QSTR + col + 4];
                a[mi][3] = Ac[(r + 8) * QSTR + col + 4];
            }
            #pragma unroll
            for (int ni = 0; ni < 8; ni++) {
                int n0 = nCol0 + ni * 8 + g;
                unsigned b[2];
                b[0] = Bc[n0 * QSTR + col];
                b[1] = Bc[n0 * QSTR + col + 4];
                mma_tf32(acc[0][ni], a[0], b);
                mma_tf32(acc[1][ni], a[1], b);
            }
        }

        // Retire staging into the other buffer.
        if (pf) {
            #pragma unroll
            for (int j = 0; j < 4; j++) {
                int idx = tid + j * 256;
                int row = idx >> 3;
                int c4 = (idx & 7) * 4;
                unsigned* p = &An[row * QSTR + c4];
                p[0] = f2tf(xa[j].x); p[1] = f2tf(xa[j].y);
                p[2] = f2tf(xa[j].z); p[3] = f2tf(xa[j].w);
                unsigned* q = &Bn[row * QSTR + c4];
                q[0] = f2tf(wb[j].x); q[1] = f2tf(wb[j].y);
                q[2] = f2tf(wb[j].z); q[3] = f2tf(wb[j].w);
            }
        }
        __syncthreads();
    }

    // Epilogue: bias + scatter into [B,H,S,hd].
    #pragma unroll
    for (int ni = 0; ni < 8; ni++) {
        int d = colInMat + nCol0 + ni * 8 + 2 * t;   // col within matrix
        int head = d >> 6;
        int dim = d & 63;
        float2 bv2 = *(const float2*)&bias[d];
        #pragma unroll
        for (int mi = 0; mi < 2; mi++) {
            #pragma unroll
            for (int half = 0; half < 2; half++) {
                int token = rowBase + mRow0 + mi * 16 + g + half * 8;
                int bidx = token >> 11;
                int s = token & (SS - 1);
                float2 o;
                o.x = acc[mi][ni][half * 2 + 0] + bv2.x;
                o.y = acc[mi][ni][half * 2 + 1] + bv2.y;
                *(float2*)&dst[(((size_t)(bidx * NH + head)) * SS + s) * HD + dim] = o;
            }
        }
    }
}

// ---------------------------------------------------------------------------
// Kernel 2: attention (unchanged from R8): tf32 MMA, m=32 warp tiles,
// shuffle-free register P via k-permutation, double buffer, 1 sync/tile.
// ---------------------------------------------------------------------------
#define KSTR 68
#define VSTR 72
#define KWORDS (64 * KSTR)          // 4352
#define VWORDS (64 * VSTR)          // 4608
#define ATTN_SMEM_BYTES ((2 * KWORDS + 2 * VWORDS) * 4)   // 71680

__global__ __launch_bounds__(128, 2) void attn_kernel(
    const float* __restrict__ mask, float* __restrict__ out)
{
    extern __shared__ unsigned smem[];
    unsigned* kbuf[2] = { smem, smem + KWORDS };
    unsigned* vbuf[2] = { smem + 2 * KWORDS, smem + 2 * KWORDS + VWORDS };

    const int tid = threadIdx.x;
    const int lane = tid & 31;
    const int w = tid >> 5;
    const int qRow0 = w * 32;
    const int t = lane & 3;
    const int g = lane >> 2;

    const int bh = blockIdx.y;
    const int b = bh >> 4;
    const int h = bh & 15;
    const int qBase = blockIdx.x * 128;

    const float* qg = g_q + (size_t)bh * SS * HD;
    const float* kg = g_k + (size_t)bh * SS * HD;
    const float* vg = g_v + (size_t)bh * SS * HD;
    const float* maskrow = mask + b * SS;

    const float scale = 0.125f;

    // Hoist Q fragments: 2 m-frags x 8 k-steps.
    unsigned a_q[2][8][4];
    #pragma unroll
    for (int mi = 0; mi < 2; mi++) {
        int r0 = qBase + qRow0 + mi * 16 + g;
        int r1 = r0 + 8;
        #pragma unroll
        for (int kk = 0; kk < 8; kk++) {
            int col = kk * 8 + t;
            a_q[mi][kk][0] = f2tf(qg[(size_t)r0 * HD + col]);
            a_q[mi][kk][1] = f2tf(qg[(size_t)r1 * HD + col]);
            a_q[mi][kk][2] = f2tf(qg[(size_t)r0 * HD + col + 4]);
            a_q[mi][kk][3] = f2tf(qg[(size_t)r1 * HD + col + 4]);
        }
    }

    const int lrow = tid >> 4;            // 0..7 (+8j)
    const int lc4 = (tid & 15) * 4;       // 0..60

    float ctx[2][8][4] = {};

    // Preload tile 0 (V rows go to permuted slots).
    #pragma unroll
    for (int j = 0; j < 8; j++) {
        int row = lrow + j * 8;
        float4 kv = *(const float4*)&kg[(size_t)row * HD + lc4];
        uint4 ku;
        ku.x = f2tf(kv.x); ku.y = f2tf(kv.y); ku.z = f2tf(kv.z); ku.w = f2tf(kv.w);
        *(uint4*)&kbuf[0][row * KSTR + lc4] = ku;
        float4 vv = *(const float4*)&vg[(size_t)row * HD + lc4];
        uint4 vu;
        vu.x = f2tf(vv.x); vu.y = f2tf(vv.y); vu.z = f2tf(vv.z); vu.w = f2tf(vv.w);
        int vslot = (row & ~7) | ((row & 7) >> 1) | ((row & 1) << 2);
        *(uint4*)&vbuf[0][vslot * VSTR + lc4] = vu;
    }
    __syncthreads();

    for (int tt = 0; tt < 32; tt++) {
        const unsigned* kc = kbuf[tt & 1];
        const unsigned* vc = vbuf[tt & 1];
        unsigned* kn = kbuf[(tt + 1) & 1];
        unsigned* vn = vbuf[(tt + 1) & 1];
        const bool pf = (tt < 31);

        float4 stg[8];
        if (pf) {
            const float* kt = kg + (size_t)((tt + 1) * 64) * HD;
            #pragma unroll
            for (int j = 0; j < 8; j++)
                stg[j] = *(const float4*)&kt[(size_t)(lrow + j * 8) * HD + lc4];
        }

        // ---- HALF 0 : keys 0..31 ----
        {
            float s[2][4][4] = {};
            #pragma unroll
            for (int kk = 0; kk < 8; kk++) {
                #pragma unroll
                for (int ni = 0; ni < 4; ni++) {
                    const unsigned* kr = &kc[(ni * 8 + g) * KSTR + kk * 8 + t];
                    unsigned bf[2] = { kr[0], kr[4] };
                    mma_tf32(s[0][ni], a_q[0][kk], bf);
                    mma_tf32(s[1][ni], a_q[1][kk], bf);
                }
            }
            unsigned pa[2][4][4];
            #pragma unroll
            for (int ni = 0; ni < 4; ni++) {
                float2 m2 = *(const float2*)&maskrow[tt * 64 + ni * 8 + 2 * t];
                #pragma unroll
                for (int mi = 0; mi < 2; mi++) {
                    float p0 = fmaxf(s[mi][ni][0] * scale + m2.x, 0.0f);
                    float p1 = fmaxf(s[mi][ni][1] * scale + m2.y, 0.0f);
                    float p2 = fmaxf(s[mi][ni][2] * scale + m2.x, 0.0f);
                    float p3 = fmaxf(s[mi][ni][3] * scale + m2.y, 0.0f);
                    pa[mi][ni][0] = f2tf(p0 * p0);
                    pa[mi][ni][1] = f2tf(p2 * p2);
                    pa[mi][ni][2] = f2tf(p1 * p1);
                    pa[mi][ni][3] = f2tf(p3 * p3);
                }
            }
            #pragma unroll
            for (int kk = 0; kk < 4; kk++) {
                #pragma unroll
                for (int ti = 0; ti < 8; ti++) {
                    unsigned bf[2];
                    bf[0] = vc[(kk * 8 + t) * VSTR + ti * 8 + g];
                    bf[1] = vc[(kk * 8 + t + 4) * VSTR + ti * 8 + g];
                    mma_tf32(ctx[0][ti], pa[0][kk], bf);
                    mma_tf32(ctx[1][ti], pa[1][kk], bf);
                }
            }
        }

        if (pf) {
            #pragma unroll
            for (int j = 0; j < 8; j++) {
                uint4 ku;
                ku.x = f2tf(stg[j].x); ku.y = f2tf(stg[j].y);
                ku.z = f2tf(stg[j].z); ku.w = f2tf(stg[j].w);
                *(uint4*)&kn[(lrow + j * 8) * KSTR + lc4] = ku;
            }
            const float* vt = vg + (size_t)((tt + 1) * 64) * HD;
            #pragma unroll
            for (int j = 0; j < 8; j++)
                stg[j] = *(const float4*)&vt[(size_t)(lrow + j * 8) * HD + lc4];
        }

        // ---- HALF 1 : keys 32..63 ----
        {
            float s[2][4][4] = {};
            #pragma unroll
            for (int kk = 0; kk < 8; kk++) {
                #pragma unroll
                for (int ni = 0; ni < 4; ni++) {
                    const unsigned* kr = &kc[((ni + 4) * 8 + g) * KSTR + kk * 8 + t];
                    unsigned bf[2] = { kr[0], kr[4] };
                    mma_tf32(s[0][ni], a_q[0][kk], bf);
                    mma_tf32(s[1][ni], a_q[1][kk], bf);
                }
            }
            unsigned pa[2][4][4];
            #pragma unroll
            for (int ni = 0; ni < 4; ni++) {
                float2 m2 = *(const float2*)&maskrow[tt * 64 + 32 + ni * 8 + 2 * t];
                #pragma unroll
                for (int mi = 0; mi < 2; mi++) {
                    float p0 = fmaxf(s[mi][ni][0] * scale + m2.x, 0.0f);
                    float p1 = fmaxf(s[mi][ni][1] * scale + m2.y, 0.0f);
                    float p2 = fmaxf(s[mi][ni][2] * scale + m2.x, 0.0f);
                    float p3 = fmaxf(s[mi][ni][3] * scale + m2.y, 0.0f);
                    pa[mi][ni][0] = f2tf(p0 * p0);
                    pa[mi][ni][1] = f2tf(p2 * p2);
                    pa[mi][ni][2] = f2tf(p1 * p1);
                    pa[mi][ni][3] = f2tf(p3 * p3);
                }
            }
            #pragma unroll
            for (int kk = 0; kk < 4; kk++) {
                #pragma unroll
                for (int ti = 0; ti < 8; ti++) {
                    unsigned bf[2];
                    bf[0] = vc[((kk + 4) * 8 + t) * VSTR + ti * 8 + g];
                    bf[1] = vc[((kk + 4) * 8 + t + 4) * VSTR + ti * 8 + g];
                    mma_tf32(ctx[0][ti], pa[0][kk], bf);
                    mma_tf32(ctx[1][ti], pa[1][kk], bf);
                }
            }
        }

        if (pf) {
            #pragma unroll
            for (int j = 0; j < 8; j++) {
                uint4 vu;
                vu.x = f2tf(stg[j].x); vu.y = f2tf(stg[j].y);
                vu.z = f2tf(stg[j].z); vu.w = f2tf(stg[j].w);
                int row = lrow + j * 8;
                int vslot = (row & ~7) | ((row & 7) >> 1) | ((row & 1) << 2);
                *(uint4*)&vn[vslot * VSTR + lc4] = vu;
            }
        }
        __syncthreads();
    }

    // Write context: out[b][s][h*64 + d].
    #pragma unroll
    for (int mi = 0; mi < 2; mi++) {
        int r0 = qBase + qRow0 + mi * 16 + g;
        float* o0 = out + ((size_t)(b * SS + r0)) * DM + h * HD;
        float* o1 = o0 + (size_t)8 * DM;
        #pragma unroll
        for (int ti = 0; ti < 8; ti++) {
            int d = ti * 8 + 2 * t;
            *(float2*)&o0[d] = make_float2(ctx[mi][ti][0], ctx[mi][ti][1]);
            *(float2*)&o1[d] = make_float2(ctx[mi][ti][2], ctx[mi][ti][3]);
        }
    }
}

extern "C" void kernel_launch(void* const* d_in, const int* in_sizes, int n_in,
                              void* d_out, int out_size)
{
    const float* x    = (const float*)d_in[0];
    const float* mask = (const float*)d_in[1];
    const float* Wq   = (const float*)d_in[2];
    const float* bq   = (const float*)d_in[3];
    const float* Wk   = (const float*)d_in[4];
    const float* bk   = (const float*)d_in[5];
    const float* Wv   = (const float*)d_in[6];
    const float* bv   = (const float*)d_in[7];
    float* out = (float*)d_out;

    cudaFuncSetAttribute(qkv_kernel,
                         cudaFuncAttributeMaxDynamicSharedMemorySize,
                         QKV_SMEM_BYTES);
    cudaFuncSetAttribute(attn_kernel,
                         cudaFuncAttributeMaxDynamicSharedMemorySize,
                         ATTN_SMEM_BYTES);

    qkv_kernel<<<dim3(3 * DM / 128, (BB * SS) / 128), 256, QKV_SMEM_BYTES>>>(
        x, Wq, bq, Wk, bk, Wv, bv);

    attn_kernel<<<dim3(SS / 128, BB * NH), 128, ATTN_SMEM_BYTES>>>(mask, out);
}

// round 10
// speedup vs baseline: 1.0046x; 1.0046x over previous
#include <cuda_runtime.h>
#include <cstdint>

#define BB 4
#define SS 2048
#define NH 16
#define HD 64
#define DM 1024

// Scratch for Q/K/V in [B, H, S, hd] layout (device globals: allocation-free).
__device__ __align__(16) float g_q[BB * NH * SS * HD];
__device__ __align__(16) float g_k[BB * NH * SS * HD];
__device__ __align__(16) float g_v[BB * NH * SS * HD];

__device__ __forceinline__ unsigned f2tf(float x) {
    unsigned u;
    asm("cvt.rna.tf32.f32 %0, %1;" : "=r"(u) : "f"(x));
    return u;
}

__device__ __forceinline__ void mma_tf32(float* c, const unsigned* a, const unsigned* b) {
    asm volatile(
        "mma.sync.aligned.m16n8k8.row.col.f32.tf32.tf32.f32 "
        "{%0,%1,%2,%3}, {%4,%5,%6,%7}, {%8,%9}, {%0,%1,%2,%3};"
        : "+f"(c[0]), "+f"(c[1]), "+f"(c[2]), "+f"(c[3])
        : "r"(a[0]), "r"(a[1]), "r"(a[2]), "r"(a[3]), "r"(b[0]), "r"(b[1]));
}

// ---------------------------------------------------------------------------
// Kernel 1: fused QKV projection, tf32 MMA, 128x128 block tile, 8 warps
// (warp = 32m x 64n). Double-buffered smem; staging split X-then-W so peak
// staging registers are 16. launch_bounds(256,2) caps regs at 128 -> 2 CTAs/SM.
// ---------------------------------------------------------------------------
#define QSTR 36
#define QTILEW (128 * QSTR)
#define QKV_SMEM_BYTES (4 * QTILEW * 4)   // 73728

__global__ __launch_bounds__(256, 2) void qkv_kernel(
    const float* __restrict__ x,
    const float* __restrict__ Wq, const float* __restrict__ bq,
    const float* __restrict__ Wk, const float* __restrict__ bk,
    const float* __restrict__ Wv, const float* __restrict__ bv)
{
    extern __shared__ unsigned qsm[];
    unsigned* As[2] = { qsm, qsm + QTILEW };
    unsigned* Bs[2] = { qsm + 2 * QTILEW, qsm + 3 * QTILEW };

    const int tid = threadIdx.x;
    const int lane = tid & 31;
    const int w = tid >> 5;
    const int wm = w & 3;
    const int wn = w >> 2;
    const int mRow0 = wm * 32;
    const int nCol0 = wn * 64;
    const int t = lane & 3;
    const int g = lane >> 2;

    const int rowBase = blockIdx.y * 128;
    const int colBase = blockIdx.x * 128;      // combined cols [0,3072)
    const int mat = colBase >> 10;             // 0=Q 1=K 2=V (no straddle)
    const int colInMat = colBase & 1023;

    const float* W    = (mat == 0) ? Wq : (mat == 1) ? Wk : Wv;
    const float* bias = (mat == 0) ? bq : (mat == 1) ? bk : bv;
    float*       dst  = (mat == 0) ? g_q : (mat == 1) ? g_k : g_v;

    // Loader mapping: idx = tid + j*256; row = idx>>3 (0..127); c4 = (idx&7)*4.
    const int lrow = tid >> 3;
    const int lc4 = (tid & 7) * 4;

    float acc[2][8][4] = {};

    // Preload chunk 0.
    #pragma unroll
    for (int j = 0; j < 4; j++) {
        int row = lrow + j * 32;
        float4 a = *(const float4*)&x[(size_t)(rowBase + row) * DM + lc4];
        unsigned* p = &As[0][row * QSTR + lc4];
        p[0] = f2tf(a.x); p[1] = f2tf(a.y); p[2] = f2tf(a.z); p[3] = f2tf(a.w);
        float4 bw = *(const float4*)&W[(size_t)(colInMat + row) * DM + lc4];
        unsigned* q = &Bs[0][row * QSTR + lc4];
        q[0] = f2tf(bw.x); q[1] = f2tf(bw.y); q[2] = f2tf(bw.z); q[3] = f2tf(bw.w);
    }
    __syncthreads();

    for (int c = 0; c < 32; c++) {
        const unsigned* Ac = As[c & 1];
        const unsigned* Bc = Bs[c & 1];
        unsigned* An = As[(c + 1) & 1];
        unsigned* Bn = Bs[(c + 1) & 1];
        const bool pf = (c < 31);
        const int kt = (c + 1) * 32;

        // Stage X for next chunk (16 regs, live through kk=0,1 only).
        float4 stg[4];
        if (pf) {
            #pragma unroll
            for (int j = 0; j < 4; j++)
                stg[j] = *(const float4*)&x[(size_t)(rowBase + lrow + j * 32) * DM + kt + lc4];
        }

        // MMAs kk = 0,1.
        #pragma unroll
        for (int kk = 0; kk < 2; kk++) {
            const int col = kk * 8 + t;
            unsigned a[2][4];
            #pragma unroll
            for (int mi = 0; mi < 2; mi++) {
                int r = mRow0 + mi * 16 + g;
                a[mi][0] = Ac[r * QSTR + col];
                a[mi][1] = Ac[(r + 8) * QSTR + col];
                a[mi][2] = Ac[r * QSTR + col + 4];
                a[mi][3] = Ac[(r + 8) * QSTR + col + 4];
            }
            #pragma unroll
            for (int ni = 0; ni < 8; ni++) {
                int n0 = nCol0 + ni * 8 + g;
                unsigned b[2];
                b[0] = Bc[n0 * QSTR + col];
                b[1] = Bc[n0 * QSTR + col + 4];
                mma_tf32(acc[0][ni], a[0], b);
                mma_tf32(acc[1][ni], a[1], b);
            }
        }

        // Retire X staging; stage W (16 regs, live through kk=2,3 only).
        if (pf) {
            #pragma unroll
            for (int j = 0; j < 4; j++) {
                unsigned* p = &An[(lrow + j * 32) * QSTR + lc4];
                p[0] = f2tf(stg[j].x); p[1] = f2tf(stg[j].y);
                p[2] = f2tf(stg[j].z); p[3] = f2tf(stg[j].w);
            }
            #pragma unroll
            for (int j = 0; j < 4; j++)
                stg[j] = *(const float4*)&W[(size_t)(colInMat + lrow + j * 32) * DM + kt + lc4];
        }

        // MMAs kk = 2,3.
        #pragma unroll
        for (int kk = 2; kk < 4; kk++) {
            const int col = kk * 8 + t;
            unsigned a[2][4];
            #pragma unroll
            for (int mi = 0; mi < 2; mi++) {
                int r = mRow0 + mi * 16 + g;
                a[mi][0] = Ac[r * QSTR + col];
                a[mi][1] = Ac[(r + 8) * QSTR + col];
                a[mi][2] = Ac[r * QSTR + col + 4];
                a[mi][3] = Ac[(r + 8) * QSTR + col + 4];
            }
            #pragma unroll
            for (int ni = 0; ni < 8; ni++) {
                int n0 = nCol0 + ni * 8 + g;
                unsigned b[2];
                b[0] = Bc[n0 * QSTR + col];
                b[1] = Bc[n0 * QSTR + col + 4];
                mma_tf32(acc[0][ni], a[0], b);
                mma_tf32(acc[1][ni], a[1], b);
            }
        }

        // Retire W staging.
        if (pf) {
            #pragma unroll
            for (int j = 0; j < 4; j++) {
                unsigned* q = &Bn[(lrow + j * 32) * QSTR + lc4];
                q[0] = f2tf(stg[j].x); q[1] = f2tf(stg[j].y);
                q[2] = f2tf(stg[j].z); q[3] = f2tf(stg[j].w);
            }
        }
        __syncthreads();
    }

    // Epilogue: bias + scatter into [B,H,S,hd].
    #pragma unroll
    for (int ni = 0; ni < 8; ni++) {
        int d = colInMat + nCol0 + ni * 8 + 2 * t;   // col within matrix
        int head = d >> 6;
        int dim = d & 63;
        float2 bv2 = *(const float2*)&bias[d];
        #pragma unroll
        for (int mi = 0; mi < 2; mi++) {
            #pragma unroll
            for (int half = 0; half < 2; half++) {
                int token = rowBase + mRow0 + mi * 16 + g + half * 8;
                int bidx = token >> 11;
                int s = token & (SS - 1);
                float2 o;
                o.x = acc[mi][ni][half * 2 + 0] + bv2.x;
                o.y = acc[mi][ni][half * 2 + 1] + bv2.y;
                *(float2*)&dst[(((size_t)(bidx * NH + head)) * SS + s) * HD + dim] = o;
            }
        }
    }
}

// ---------------------------------------------------------------------------
// Kernel 2: attention (unchanged, proven 449us): tf32 MMA, m=32 warp tiles,
// shuffle-free register P via k-permutation, double buffer, 1 sync/tile.
// ---------------------------------------------------------------------------
#define KSTR 68
#define VSTR 72
#define KWORDS (64 * KSTR)          // 4352
#define VWORDS (64 * VSTR)          // 4608
#define ATTN_SMEM_BYTES ((2 * KWORDS + 2 * VWORDS) * 4)   // 71680

__global__ __launch_bounds__(128, 2) void attn_kernel(
    const float* __restrict__ mask, float* __restrict__ out)
{
    extern __shared__ unsigned smem[];
    unsigned* kbuf[2] = { smem, smem + KWORDS };
    unsigned* vbuf[2] = { smem + 2 * KWORDS, smem + 2 * KWORDS + VWORDS };

    const int tid = threadIdx.x;
    const int lane = tid & 31;
    const int w = tid >> 5;
    const int qRow0 = w * 32;
    const int t = lane & 3;
    const int g = lane >> 2;

    const int bh = blockIdx.y;
    const int b = bh >> 4;
    const int h = bh & 15;
    const int qBase = blockIdx.x * 128;

    const float* qg = g_q + (size_t)bh * SS * HD;
    const float* kg = g_k + (size_t)bh * SS * HD;
    const float* vg = g_v + (size_t)bh * SS * HD;
    const float* maskrow = mask + b * SS;

    const float scale = 0.125f;

    // Hoist Q fragments: 2 m-frags x 8 k-steps.
    unsigned a_q[2][8][4];
    #pragma unroll
    for (int mi = 0; mi < 2; mi++) {
        int r0 = qBase + qRow0 + mi * 16 + g;
        int r1 = r0 + 8;
        #pragma unroll
        for (int kk = 0; kk < 8; kk++) {
            int col = kk * 8 + t;
            a_q[mi][kk][0] = f2tf(qg[(size_t)r0 * HD + col]);
            a_q[mi][kk][1] = f2tf(qg[(size_t)r1 * HD + col]);
            a_q[mi][kk][2] = f2tf(qg[(size_t)r0 * HD + col + 4]);
            a_q[mi][kk][3] = f2tf(qg[(size_t)r1 * HD + col + 4]);
        }
    }

    const int lrow = tid >> 4;            // 0..7 (+8j)
    const int lc4 = (tid & 15) * 4;       // 0..60

    float ctx[2][8][4] = {};

    // Preload tile 0 (V rows go to permuted slots).
    #pragma unroll
    for (int j = 0; j < 8; j++) {
        int row = lrow + j * 8;
        float4 kv = *(const float4*)&kg[(size_t)row * HD + lc4];
        uint4 ku;
        ku.x = f2tf(kv.x); ku.y = f2tf(kv.y); ku.z = f2tf(kv.z); ku.w = f2tf(kv.w);
        *(uint4*)&kbuf[0][row * KSTR + lc4] = ku;
        float4 vv = *(const float4*)&vg[(size_t)row * HD + lc4];
        uint4 vu;
        vu.x = f2tf(vv.x); vu.y = f2tf(vv.y); vu.z = f2tf(vv.z); vu.w = f2tf(vv.w);
        int vslot = (row & ~7) | ((row & 7) >> 1) | ((row & 1) << 2);
        *(uint4*)&vbuf[0][vslot * VSTR + lc4] = vu;
    }
    __syncthreads();

    for (int tt = 0; tt < 32; tt++) {
        const unsigned* kc = kbuf[tt & 1];
        const unsigned* vc = vbuf[tt & 1];
        unsigned* kn = kbuf[(tt + 1) & 1];
        unsigned* vn = vbuf[(tt + 1) & 1];
        const bool pf = (tt < 31);

        float4 stg[8];
        if (pf) {
            const float* kt = kg + (size_t)((tt + 1) * 64) * HD;
            #pragma unroll
            for (int j = 0; j < 8; j++)
                stg[j] = *(const float4*)&kt[(size_t)(lrow + j * 8) * HD + lc4];
        }

        // ---- HALF 0 : keys 0..31 ----
        {
            float s[2][4][4] = {};
            #pragma unroll
            for (int kk = 0; kk < 8; kk++) {
                #pragma unroll
                for (int ni = 0; ni < 4; ni++) {
                    const unsigned* kr = &kc[(ni * 8 + g) * KSTR + kk * 8 + t];
                    unsigned bf[2] = { kr[0], kr[4] };
                    mma_tf32(s[0][ni], a_q[0][kk], bf);
                    mma_tf32(s[1][ni], a_q[1][kk], bf);
                }
            }
            unsigned pa[2][4][4];
            #pragma unroll
            for (int ni = 0; ni < 4; ni++) {
                float2 m2 = *(const float2*)&maskrow[tt * 64 + ni * 8 + 2 * t];
                #pragma unroll
                for (int mi = 0; mi < 2; mi++) {
                    float p0 = fmaxf(s[mi][ni][0] * scale + m2.x, 0.0f);
                    float p1 = fmaxf(s[mi][ni][1] * scale + m2.y, 0.0f);
                    float p2 = fmaxf(s[mi][ni][2] * scale + m2.x, 0.0f);
                    float p3 = fmaxf(s[mi][ni][3] * scale + m2.y, 0.0f);
                    pa[mi][ni][0] = f2tf(p0 * p0);
                    pa[mi][ni][1] = f2tf(p2 * p2);
                    pa[mi][ni][2] = f2tf(p1 * p1);
                    pa[mi][ni][3] = f2tf(p3 * p3);
                }
            }
            #pragma unroll
            for (int kk = 0; kk < 4; kk++) {
                #pragma unroll
                for (int ti = 0; ti < 8; ti++) {
                    unsigned bf[2];
                    bf[0] = vc[(kk * 8 + t) * VSTR + ti * 8 + g];
                    bf[1] = vc[(kk * 8 + t + 4) * VSTR + ti * 8 + g];
                    mma_tf32(ctx[0][ti], pa[0][kk], bf);
                    mma_tf32(ctx[1][ti], pa[1][kk], bf);
                }
            }
        }

        if (pf) {
            #pragma unroll
            for (int j = 0; j < 8; j++) {
                uint4 ku;
                ku.x = f2tf(stg[j].x); ku.y = f2tf(stg[j].y);
                ku.z = f2tf(stg[j].z); ku.w = f2tf(stg[j].w);
                *(uint4*)&kn[(lrow + j * 8) * KSTR + lc4] = ku;
            }
            const float* vt = vg + (size_t)((tt + 1) * 64) * HD;
            #pragma unroll
            for (int j = 0; j < 8; j++)
                stg[j] = *(const float4*)&vt[(size_t)(lrow + j * 8) * HD + lc4];
        }

        // ---- HALF 1 : keys 32..63 ----
        {
            float s[2][4][4] = {};
            #pragma unroll
            for (int kk = 0; kk < 8; kk++) {
                #pragma unroll
                for (int ni = 0; ni < 4; ni++) {
                    const unsigned* kr = &kc[((ni + 4) * 8 + g) * KSTR + kk * 8 + t];
                    unsigned bf[2] = { kr[0], kr[4] };
                    mma_tf32(s[0][ni], a_q[0][kk], bf);
                    mma_tf32(s[1][ni], a_q[1][kk], bf);
                }
            }
            unsigned pa[2][4][4];
            #pragma unroll
            for (int ni = 0; ni < 4; ni++) {
                float2 m2 = *(const float2*)&maskrow[tt * 64 + 32 + ni * 8 + 2 * t];
                #pragma unroll
                for (int mi = 0; mi < 2; mi++) {
                    float p0 = fmaxf(s[mi][ni][0] * scale + m2.x, 0.0f);
                    float p1 = fmaxf(s[mi][ni][1] * scale + m2.y, 0.0f);
                    float p2 = fmaxf(s[mi][ni][2] * scale + m2.x, 0.0f);
                    float p3 = fmaxf(s[mi][ni][3] * scale + m2.y, 0.0f);
                    pa[mi][ni][0] = f2tf(p0 * p0);
                    pa[mi][ni][1] = f2tf(p2 * p2);
                    pa[mi][ni][2] = f2tf(p1 * p1);
                    pa[mi][ni][3] = f2tf(p3 * p3);
                }
            }
            #pragma unroll
            for (int kk = 0; kk < 4; kk++) {
                #pragma unroll
                for (int ti = 0; ti < 8; ti++) {
                    unsigned bf[2];
                    bf[0] = vc[((kk + 4) * 8 + t) * VSTR + ti * 8 + g];
                    bf[1] = vc[((kk + 4) * 8 + t + 4) * VSTR + ti * 8 + g];
                    mma_tf32(ctx[0][ti], pa[0][kk], bf);
                    mma_tf32(ctx[1][ti], pa[1][kk], bf);
                }
            }
        }

        if (pf) {
            #pragma unroll
            for (int j = 0; j < 8; j++) {
                uint4 vu;
                vu.x = f2tf(stg[j].x); vu.y = f2tf(stg[j].y);
                vu.z = f2tf(stg[j].z); vu.w = f2tf(stg[j].w);
                int row = lrow + j * 8;
                int vslot = (row & ~7) | ((row & 7) >> 1) | ((row & 1) << 2);
                *(uint4*)&vn[vslot * VSTR + lc4] = vu;
            }
        }
        __syncthreads();
    }

    // Write context: out[b][s][h*64 + d].
    #pragma unroll
    for (int mi = 0; mi < 2; mi++) {
        int r0 = qBase + qRow0 + mi * 16 + g;
        float* o0 = out + ((size_t)(b * SS + r0)) * DM + h * HD;
        float* o1 = o0 + (size_t)8 * DM;
        #pragma unroll
        for (int ti = 0; ti < 8; ti++) {
            int d = ti * 8 + 2 * t;
            *(float2*)&o0[d] = make_float2(ctx[mi][ti][0], ctx[mi][ti][1]);
            *(float2*)&o1[d] = make_float2(ctx[mi][ti][2], ctx[mi][ti][3]);
        }
    }
}

extern "C" void kernel_launch(void* const* d_in, const int* in_sizes, int n_in,
                              void* d_out, int out_size)
{
    const float* x    = (const float*)d_in[0];
    const float* mask = (const float*)d_in[1];
    const float* Wq   = (const float*)d_in[2];
    const float* bq   = (const float*)d_in[3];
    const float* Wk   = (const float*)d_in[4];
    const float* bk   = (const float*)d_in[5];
    const float* Wv   = (const float*)d_in[6];
    const float* bv   = (const float*)d_in[7];
    float* out = (float*)d_out;

    cudaFuncSetAttribute(qkv_kernel,
                         cudaFuncAttributeMaxDynamicSharedMemorySize,
                         QKV_SMEM_BYTES);
    cudaFuncSetAttribute(attn_kernel,
                         cudaFuncAttributeMaxDynamicSharedMemorySize,
                         ATTN_SMEM_BYTES);

    qkv_kernel<<<dim3(3 * DM / 128, (BB * SS) / 128), 256, QKV_SMEM_BYTES>>>(
        x, Wq, bq, Wk, bk, Wv, bv);

    attn_kernel<<<dim3(SS / 128, BB * NH), 128, ATTN_SMEM_BYTES>>>(mask, out);
}